// round 9
// baseline (speedup 1.0000x reference)
#include <cuda_runtime.h>

// RGBuvHistBlock: x [8,3,256,256] f32 in [0,1]; bin_vals [64] = linspace(-1,1).
// hist[nc][b] = sum_p exp(-((2x-1)-b)^2/(2*0.02^2)), normalized per nc.
//
// R9: R8's 12-bin quad window (3 LDS.128 + 3 STS.128/pixel, 3 EX2 + power
// chain) + DUAL alternating hist copies: even pixels hit copy0, odd copy1,
// so consecutive RMW chains are provably independent -> 2x ILP. 64KB dynamic
// smem, 2.6 blocks/SM fully resident at SPLITS=16.

#define NC_TOTAL   24
#define PIX_PER_NC 65536
#define HB         64
#define SPLITS     16
#define CHUNK      4096
#define NT         128
#define NQUAD      16            // 64 bins as 16 float4 quads
#define HCELLS     (NQUAD * NT)  // float4 cells per copy

#define DS_   1.3481298394f      // scaled bin spacing = sqrt(1250*log2e)*2/63
#define KC_   7.41471412f        // 5.5*DS
// K_m = 2^{-(m*DS)^2}, m = 0.5,...,5.5
#define K05  0.7298330f
#define K15  0.0587498f
#define K25  3.806934e-4f
#define K35  1.985730e-7f
#define K45  8.337990e-12f
#define K55  2.818250e-17f

#define SMEM_BYTES ((2 * HCELLS + NT) * 16)

__device__ float    g_part[NC_TOTAL * SPLITS * HB];
__device__ unsigned g_cnt[NC_TOTAL];

__device__ __forceinline__ float ex2f(float a) {
    float r;
    asm("ex2.approx.ftz.f32 %0, %1;" : "=f"(r) : "f"(a));
    return r;
}

__global__ __launch_bounds__(NT) void hist_fused_kernel(
    const float* __restrict__ x, const float* __restrict__ bin_vals,
    float* __restrict__ out)
{
    extern __shared__ float4 smem4[];
    float4* hist4 = smem4;                 // [2][NQUAD][NT]
    float4* racc4 = smem4 + 2 * HCELLS;    // [NT]

    __shared__ float ws[2];
    __shared__ int   slast;

    const int nc    = blockIdx.y;
    const int split = blockIdx.x;
    const int tid   = threadIdx.x;

    // Zero both copies (32 STS.128 per thread).
#pragma unroll
    for (int i = 0; i < 2 * NQUAD; ++i)
        hist4[tid + i * NT] = make_float4(0.f, 0.f, 0.f, 0.f);
    __syncthreads();

    const float4* xp = reinterpret_cast<const float4*>(
        x + (size_t)nc * PIX_PER_NC + (size_t)split * CHUNK);

#pragma unroll 2
    for (int it = 0; it < CHUNK / (4 * NT); ++it) {
        float4 v = xp[tid + it * NT];
        float pv[4] = {v.x, v.y, v.z, v.w};
#pragma unroll
        for (int p = 0; p < 4; ++p) {
            float u  = pv[p] * 63.0f;
            int   q  = __float2int_rn(fmaf(u, 0.25f, -1.375f));
            q = min(max(q, 0), 13);
            float c  = fmaf(u - (float)(4 * q), DS_, -KC_);

            float A  = ex2f(-c * c);
            float B  = ex2f(-c * DS_);
            float Bp = ex2f(c * DS_);

            float B2 = B * B,   P2 = Bp * Bp;
            float B3 = B2 * B,  P3 = P2 * Bp;
            float B5 = B3 * B2, P5 = P3 * P2;
            float B7 = B5 * B2, P7 = P5 * P2;
            float B9 = B7 * B2, P9 = P7 * P2;
            float B11 = B9 * B2, P11 = P9 * P2;

            float t0 = B11 * K55, t1 = B9 * K45, t2  = B7 * K35;
            float t3 = B5 * K25,  t4 = B3 * K15, t5  = B  * K05;
            float t6 = Bp * K05,  t7 = P3 * K15, t8  = P5 * K25;
            float t9 = P7 * K35, t10 = P9 * K45, t11 = P11 * K55;

            // Alternate copies: p&1 selects; offset is compile-time per unrolled p.
            float4* hp = hist4 + (p & 1) * HCELLS + q * NT + tid;
            float4 h0 = hp[0 * NT];
            float4 h1 = hp[1 * NT];
            float4 h2 = hp[2 * NT];
            h0.x = fmaf(A, t0,  h0.x); h0.y = fmaf(A, t1,  h0.y);
            h0.z = fmaf(A, t2,  h0.z); h0.w = fmaf(A, t3,  h0.w);
            h1.x = fmaf(A, t4,  h1.x); h1.y = fmaf(A, t5,  h1.y);
            h1.z = fmaf(A, t6,  h1.z); h1.w = fmaf(A, t7,  h1.w);
            h2.x = fmaf(A, t8,  h2.x); h2.y = fmaf(A, t9,  h2.y);
            h2.z = fmaf(A, t10, h2.z); h2.w = fmaf(A, t11, h2.w);
            hp[0 * NT] = h0;
            hp[1 * NT] = h1;
            hp[2 * NT] = h2;
        }
    }
    __syncthreads();

    // Reduce phase 1: thread (Q=tid>>3, k=tid&7) sums 16 cells of quad Q in
    // each copy (32 LDS.128).
    {
        const int Q = tid >> 3, k = tid & 7;
        const float4* hq0 = hist4 + Q * NT + k * 16;
        const float4* hq1 = hq0 + HCELLS;
        float4 acc = make_float4(0.f, 0.f, 0.f, 0.f);
#pragma unroll
        for (int i = 0; i < 16; ++i) {
            float4 a0 = hq0[i];
            float4 a1 = hq1[i];
            acc.x += a0.x + a1.x; acc.y += a0.y + a1.y;
            acc.z += a0.z + a1.z; acc.w += a0.w + a1.w;
        }
        racc4[tid] = acc;
    }
    __syncthreads();

    // Reduce phase 2: bin b sums its component over 8 partials.
    if (tid < HB) {
        const int Q = tid >> 2, comp = tid & 3;
        const float* rf = reinterpret_cast<const float*>(racc4);
        float s = 0.0f;
#pragma unroll
        for (int k = 0; k < 8; ++k)
            s += rf[(Q * 8 + k) * 4 + comp];
        g_part[((size_t)nc * SPLITS + split) * HB + tid] = s;
    }
    __syncthreads();

    // Last block per nc reduces + normalizes.
    if (tid == 0) {
        __threadfence();
        unsigned old = atomicAdd(&g_cnt[nc], 1u);
        slast = (old == SPLITS - 1);
    }
    __syncthreads();
    if (!slast) return;
    __threadfence();

    float bsum = 0.0f;
    if (tid < HB) {
        const float* p = g_part + (size_t)nc * SPLITS * HB + tid;
#pragma unroll
        for (int sp = 0; sp < SPLITS; ++sp)
            bsum += p[(size_t)sp * HB];
    }
    float v = (tid < HB) ? bsum : 0.0f;
    float r = v;
#pragma unroll
    for (int o = 16; o; o >>= 1) r += __shfl_xor_sync(0xffffffffu, r, o);
    if (tid == 0)  ws[0] = r;
    if (tid == 32) ws[1] = r;
    __syncthreads();
    float tot = ws[0] + ws[1];

    if (tid < HB)
        out[nc * HB + tid] = v / (tot + 1e-8f);

    if (tid == 0) g_cnt[nc] = 0;   // reset for next graph replay
}

extern "C" void kernel_launch(void* const* d_in, const int* in_sizes, int n_in,
                              void* d_out, int out_size) {
    const float* x        = (const float*)d_in[0];
    const float* bin_vals = (const float*)d_in[1];
    float* out            = (float*)d_out;

    static int smem_set = 0;
    if (!smem_set) {
        cudaFuncSetAttribute(hist_fused_kernel,
                             cudaFuncAttributeMaxDynamicSharedMemorySize,
                             SMEM_BYTES);
        smem_set = 1;
    }

    dim3 grid(SPLITS, NC_TOTAL);
    hist_fused_kernel<<<grid, NT, SMEM_BYTES>>>(x, bin_vals, out);
}

// round 10
// speedup vs baseline: 2.2162x; 2.2162x over previous
#include <cuda_runtime.h>

// RGBuvHistBlock: x [8,3,256,256] f32 in [0,1]; bin_vals [64] = linspace(-1,1).
// hist[nc][b] = sum_p exp(-((2x-1)-b)^2/(2*0.02^2)), normalized per nc.
//
// R10: R7's floor-achieving mainloop (float2-paired 8-bin window: 4 LDS.64 +
// 4 STS.64 per pixel, 2 EX2 + mul chain) at SPLITS=32 (5.2 warps/SMSP), with
// the overhead fixed: float4 block reduce (16 LDS.128/thread, bank-rotated)
// instead of 64 scalar LDS. Model: LSU floor 10.6k cyc/SM + ~2.5k overhead.

#define NC_TOTAL   24
#define PIX_PER_NC 65536
#define HB         64
#define SPLITS     32
#define CHUNK      2048
#define NT         128
#define NPAIR      32            // 64 bins as 32 float2 pairs

#define SA    42.46608994f       // sqrt(1250*log2e)
#define SA2   84.93217988f
#define DS    1.34812984f        // scaled bin spacing
#define TWO_D 2.69625968f
// c_j = 2^{-j^2*DS^2}
#define C1_  0.2837213f
#define C2_  6.479897e-3f
#define C3_  1.191316e-5f
#define C4_  1.763085e-9f
#define C5_  2.100399e-14f
#define C6_  2.014225e-20f
#define C7_  1.554903e-27f

__device__ float    g_part[NC_TOTAL * SPLITS * HB];
__device__ unsigned g_cnt[NC_TOTAL];

__device__ __forceinline__ float ex2f(float a) {
    float r;
    asm("ex2.approx.ftz.f32 %0, %1;" : "=f"(r) : "f"(a));
    return r;
}

__global__ __launch_bounds__(NT) void hist_fused_kernel(
    const float* __restrict__ x, const float* __restrict__ bin_vals,
    float* __restrict__ out)
{
    const int nc    = blockIdx.y;
    const int split = blockIdx.x;
    const int tid   = threadIdx.x;

    __shared__ float2 hist2[NPAIR * NT];   // 32KB: (pair p, thread t) -> hist2[p*NT+t]
    __shared__ float2 racc2[NT];           // 1KB: 4 partials per pair
    __shared__ float  ws[2];
    __shared__ int    slast;

    // Zero (16 STS.128 per thread).
    {
        float4* hz = reinterpret_cast<float4*>(hist2);
#pragma unroll
        for (int i = 0; i < (NPAIR * NT) / 2 / NT; ++i)
            hz[tid + i * NT] = make_float4(0.f, 0.f, 0.f, 0.f);
    }
    __syncthreads();

    const float4* xp = reinterpret_cast<const float4*>(
        x + (size_t)nc * PIX_PER_NC + (size_t)split * CHUNK);

#pragma unroll 2
    for (int it = 0; it < CHUNK / (4 * NT); ++it) {
        float4 v = xp[tid + it * NT];
        float pv[4] = {v.x, v.y, v.z, v.w};
#pragma unroll
        for (int p = 0; p < 4; ++p) {
            float vf = pv[p];
            float sp = vf * SA2;                       // s' in [0, 2SA]; bin j at j*DS
            int jc   = min(max(__float2int_rn(vf * 63.0f), 3), 60);
            int p0   = (jc - 3) >> 1;                  // window bins [2p0, 2p0+7]
            float ds = fmaf((float)p0, -TWO_D, sp);    // dist to bin 2p0

            float g  = ex2f(-ds * ds);                 // 2^{-ds^2}
            float r  = ex2f(ds * TWO_D);               // 2^{2*DS*ds}
            float r2 = r * r;
            float r3 = r2 * r;
            float r4 = r2 * r2;
            float gr4 = g * r4;                        // overflow-safe grouping
            float w0 = g;
            float w1 = g * (r  * C1_);
            float w2 = g * (r2 * C2_);
            float w3 = g * (r3 * C3_);
            float w4 = gr4 * C4_;
            float w5 = gr4 * (r  * C5_);
            float w6 = gr4 * (r2 * C6_);
            float w7 = gr4 * (r3 * C7_);

            float2* hp = hist2 + p0 * NT + tid;
            float2 h0 = hp[0 * NT];
            float2 h1 = hp[1 * NT];
            float2 h2 = hp[2 * NT];
            float2 h3 = hp[3 * NT];
            h0.x += w0; h0.y += w1;
            h1.x += w2; h1.y += w3;
            h2.x += w4; h2.y += w5;
            h3.x += w6; h3.y += w7;
            hp[0 * NT] = h0;
            hp[1 * NT] = h1;
            hp[2 * NT] = h2;
            hp[3 * NT] = h3;
        }
    }
    __syncthreads();

    // Reduce phase 1 (float4 view: 2048 float4; float4 f = pair P = f>>6,
    // holding bins (2P,2P+1) for threads 2j,2j+1). Thread (P=tid>>2, quarter
    // tid&3) sums 16 float4s, index rotated by tid to avoid phase conflicts.
    {
        const float4* fv = reinterpret_cast<const float4*>(hist2);
        const int P  = tid >> 2;
        const int jb = (tid & 3) * 16;
        float4 acc = make_float4(0.f, 0.f, 0.f, 0.f);
#pragma unroll
        for (int i = 0; i < 16; ++i) {
            int k = jb + ((i + tid) & 15);             // covers jb..jb+15, rotated
            float4 hv = fv[P * 64 + k];
            acc.x += hv.x; acc.y += hv.y; acc.z += hv.z; acc.w += hv.w;
        }
        racc2[tid] = make_float2(acc.x + acc.z, acc.y + acc.w);  // (bin 2P, bin 2P+1)
    }
    __syncthreads();

    // Reduce phase 2: bin b sums its 4 partials.
    if (tid < HB) {
        const int pr = tid >> 1, comp = tid & 1;
        const float* rf = reinterpret_cast<const float*>(racc2);
        float s = 0.0f;
#pragma unroll
        for (int k = 0; k < 4; ++k)
            s += rf[(pr * 4 + k) * 2 + comp];
        g_part[((size_t)nc * SPLITS + split) * HB + tid] = s;
    }
    __syncthreads();

    // Last block per nc reduces + normalizes.
    if (tid == 0) {
        __threadfence();
        unsigned old = atomicAdd(&g_cnt[nc], 1u);
        slast = (old == SPLITS - 1);
    }
    __syncthreads();
    if (!slast) return;
    __threadfence();

    float bsum = 0.0f;
    if (tid < HB) {
        const float* p = g_part + (size_t)nc * SPLITS * HB + tid;
#pragma unroll
        for (int sp = 0; sp < SPLITS; ++sp)
            bsum += p[(size_t)sp * HB];
    }
    float v = (tid < HB) ? bsum : 0.0f;
    float r = v;
#pragma unroll
    for (int o = 16; o; o >>= 1) r += __shfl_xor_sync(0xffffffffu, r, o);
    if (tid == 0)  ws[0] = r;
    if (tid == 32) ws[1] = r;
    __syncthreads();
    float tot = ws[0] + ws[1];

    if (tid < HB)
        out[nc * HB + tid] = v / (tot + 1e-8f);

    if (tid == 0) g_cnt[nc] = 0;   // reset for next graph replay
}

extern "C" void kernel_launch(void* const* d_in, const int* in_sizes, int n_in,
                              void* d_out, int out_size) {
    const float* x        = (const float*)d_in[0];
    const float* bin_vals = (const float*)d_in[1];
    float* out            = (float*)d_out;

    dim3 grid(SPLITS, NC_TOTAL);
    hist_fused_kernel<<<grid, NT>>>(x, bin_vals, out);
}

// round 11
// speedup vs baseline: 2.6925x; 1.2149x over previous
#include <cuda_runtime.h>

// RGBuvHistBlock: x [8,3,256,256] f32 in [0,1]; bin_vals [64] = linspace(-1,1).
// hist[nc][b] = sum_p exp(-((2x-1)-b)^2/(2*0.02^2)), normalized per nc.
//
// R11 = the proven-best pieces combined:
//   - R7 mainloop: float2-paired 8-bin window, 4 LDS.64 + 4 STS.64 + 2 EX2
//     per pixel, weights precomputed then plain adds (short batched chains).
//     Runs at the smem issue floor (4 cyc/warp-op).
//   - R10 reduce: float4 view, bank-rotated, 16 LDS.128/thread.
//   - SPLITS=16 (384 blocks): the only grid shape whose harness wall tracks
//     the kernel time (every 768-block variant walls at ~13us).

#define NC_TOTAL   24
#define PIX_PER_NC 65536
#define HB         64
#define SPLITS     16
#define CHUNK      4096
#define NT         128
#define NPAIR      32            // 64 bins as 32 float2 pairs

#define SA    42.46608994f       // sqrt(1250*log2e)
#define SA2   84.93217988f
#define DS    1.34812984f        // scaled bin spacing
#define TWO_D 2.69625968f
// c_j = 2^{-j^2*DS^2}
#define C1_  0.2837213f
#define C2_  6.479897e-3f
#define C3_  1.191316e-5f
#define C4_  1.763085e-9f
#define C5_  2.100399e-14f
#define C6_  2.014225e-20f
#define C7_  1.554903e-27f

__device__ float    g_part[NC_TOTAL * SPLITS * HB];
__device__ unsigned g_cnt[NC_TOTAL];

__device__ __forceinline__ float ex2f(float a) {
    float r;
    asm("ex2.approx.ftz.f32 %0, %1;" : "=f"(r) : "f"(a));
    return r;
}

__global__ __launch_bounds__(NT) void hist_fused_kernel(
    const float* __restrict__ x, const float* __restrict__ bin_vals,
    float* __restrict__ out)
{
    const int nc    = blockIdx.y;
    const int split = blockIdx.x;
    const int tid   = threadIdx.x;

    __shared__ float2 hist2[NPAIR * NT];   // 32KB: (pair p, thread t) -> hist2[p*NT+t]
    __shared__ float2 racc2[NT];           // 1KB: 4 partials per pair
    __shared__ float  ws[2];
    __shared__ int    slast;

    // Zero (16 STS.128 per thread).
    {
        float4* hz = reinterpret_cast<float4*>(hist2);
#pragma unroll
        for (int i = 0; i < (NPAIR * NT) / 2 / NT; ++i)
            hz[tid + i * NT] = make_float4(0.f, 0.f, 0.f, 0.f);
    }
    __syncthreads();

    const float4* xp = reinterpret_cast<const float4*>(
        x + (size_t)nc * PIX_PER_NC + (size_t)split * CHUNK);

#pragma unroll 2
    for (int it = 0; it < CHUNK / (4 * NT); ++it) {
        float4 v = xp[tid + it * NT];
        float pv[4] = {v.x, v.y, v.z, v.w};
#pragma unroll
        for (int p = 0; p < 4; ++p) {
            float vf = pv[p];
            float sp = vf * SA2;                       // s' in [0, 2SA]; bin j at j*DS
            int jc   = min(max(__float2int_rn(vf * 63.0f), 3), 60);
            int p0   = (jc - 3) >> 1;                  // window bins [2p0, 2p0+7]
            float ds = fmaf((float)p0, -TWO_D, sp);    // dist to bin 2p0

            float g  = ex2f(-ds * ds);                 // 2^{-ds^2}
            float r  = ex2f(ds * TWO_D);               // 2^{2*DS*ds}
            float r2 = r * r;
            float r3 = r2 * r;
            float r4 = r2 * r2;
            float gr4 = g * r4;                        // overflow-safe grouping
            float w0 = g;
            float w1 = g * (r  * C1_);
            float w2 = g * (r2 * C2_);
            float w3 = g * (r3 * C3_);
            float w4 = gr4 * C4_;
            float w5 = gr4 * (r  * C5_);
            float w6 = gr4 * (r2 * C6_);
            float w7 = gr4 * (r3 * C7_);

            float2* hp = hist2 + p0 * NT + tid;
            float2 h0 = hp[0 * NT];
            float2 h1 = hp[1 * NT];
            float2 h2 = hp[2 * NT];
            float2 h3 = hp[3 * NT];
            h0.x += w0; h0.y += w1;
            h1.x += w2; h1.y += w3;
            h2.x += w4; h2.y += w5;
            h3.x += w6; h3.y += w7;
            hp[0 * NT] = h0;
            hp[1 * NT] = h1;
            hp[2 * NT] = h2;
            hp[3 * NT] = h3;
        }
    }
    __syncthreads();

    // Reduce phase 1 (float4 view: 2048 float4; float4 index f -> pair P=f>>6,
    // holds bins (2P,2P+1) for two adjacent threads). Thread (P=tid>>2,
    // quarter tid&3) sums 16 float4s, rotated to avoid phase conflicts.
    {
        const float4* fv = reinterpret_cast<const float4*>(hist2);
        const int P  = tid >> 2;
        const int jb = (tid & 3) * 16;
        float4 acc = make_float4(0.f, 0.f, 0.f, 0.f);
#pragma unroll
        for (int i = 0; i < 16; ++i) {
            int k = jb + ((i + tid) & 15);
            float4 hv = fv[P * 64 + k];
            acc.x += hv.x; acc.y += hv.y; acc.z += hv.z; acc.w += hv.w;
        }
        racc2[tid] = make_float2(acc.x + acc.z, acc.y + acc.w);  // (bin 2P, bin 2P+1)
    }
    __syncthreads();

    // Reduce phase 2: bin b sums its 4 partials.
    if (tid < HB) {
        const int pr = tid >> 1, comp = tid & 1;
        const float* rf = reinterpret_cast<const float*>(racc2);
        float s = 0.0f;
#pragma unroll
        for (int k = 0; k < 4; ++k)
            s += rf[(pr * 4 + k) * 2 + comp];
        g_part[((size_t)nc * SPLITS + split) * HB + tid] = s;
    }
    __syncthreads();

    // Last block per nc reduces + normalizes.
    if (tid == 0) {
        __threadfence();
        unsigned old = atomicAdd(&g_cnt[nc], 1u);
        slast = (old == SPLITS - 1);
    }
    __syncthreads();
    if (!slast) return;
    __threadfence();

    float bsum = 0.0f;
    if (tid < HB) {
        const float* p = g_part + (size_t)nc * SPLITS * HB + tid;
#pragma unroll
        for (int sp = 0; sp < SPLITS; ++sp)
            bsum += p[(size_t)sp * HB];
    }
    float v = (tid < HB) ? bsum : 0.0f;
    float r = v;
#pragma unroll
    for (int o = 16; o; o >>= 1) r += __shfl_xor_sync(0xffffffffu, r, o);
    if (tid == 0)  ws[0] = r;
    if (tid == 32) ws[1] = r;
    __syncthreads();
    float tot = ws[0] + ws[1];

    if (tid < HB)
        out[nc * HB + tid] = v / (tot + 1e-8f);

    if (tid == 0) g_cnt[nc] = 0;   // reset for next graph replay
}

extern "C" void kernel_launch(void* const* d_in, const int* in_sizes, int n_in,
                              void* d_out, int out_size) {
    const float* x        = (const float*)d_in[0];
    const float* bin_vals = (const float*)d_in[1];
    float* out            = (float*)d_out;

    dim3 grid(SPLITS, NC_TOTAL);
    hist_fused_kernel<<<grid, NT>>>(x, bin_vals, out);
}